// round 5
// baseline (speedup 1.0000x reference)
#include <cuda_runtime.h>
#include <cstdint>

#define NDIM 16
#define MAXN 50048

__device__ float g_deg[MAXN];
__device__ float g_dinv[MAXN];

// ---------- small utility kernels ----------
__global__ void init_kernel(const float* __restrict__ x, float* __restrict__ out, int n) {
    int i = blockIdx.x * blockDim.x + threadIdx.x;
    int nd = n * NDIM;
    if (i < nd) out[i] = x[i];
    if (i < n) g_deg[i] = 0.f;
}

__global__ void deg_kernel(const int* __restrict__ ei, int E, int n) {
    int e = blockIdx.x * blockDim.x + threadIdx.x;
    if (e >= E) return;
    int s = ei[e], d = ei[E + e];
    if ((unsigned)s < (unsigned)n) atomicAdd(&g_deg[s], 1.f);
    if ((unsigned)d < (unsigned)n) atomicAdd(&g_deg[d], 1.f);
}

__global__ void dinv_kernel(int n) {
    int i = blockIdx.x * blockDim.x + threadIdx.x;
    if (i < n) g_dinv[i] = 1.f / sqrtf(fmaxf(g_deg[i], 1e-5f));
}

__global__ void relu_kernel(float* __restrict__ out, int nd) {
    int i = blockIdx.x * blockDim.x + threadIdx.x;
    if (i < nd) out[i] = fmaxf(out[i], 0.f);
}

// ---------- main edge kernel: one thread per edge, both MLP dirs fused ----------
__global__ void __launch_bounds__(128)
edge_kernel(const float* __restrict__ x, const int* __restrict__ ei,
            const float* __restrict__ W1, const float* __restrict__ b1,
            const float* __restrict__ W2, const float* __restrict__ b2,
            float* __restrict__ out, int E, int n)
{
    // sW1[k][j] = W1[j][k]  (transposed: j contiguous -> LDS.128 over j)
    __shared__ __align__(16) float sW1[32 * 64];
    // sW2[i][j] = W2[i][j]  (j contiguous)
    __shared__ __align__(16) float sW2[16 * 64];
    __shared__ float sb1[64];
    __shared__ float sb2[16];

    for (int idx = threadIdx.x; idx < 64 * 32; idx += blockDim.x) {
        int j = idx >> 5, k = idx & 31;
        sW1[k * 64 + j] = W1[idx];
    }
    for (int idx = threadIdx.x; idx < 16 * 64; idx += blockDim.x) sW2[idx] = W2[idx];
    if (threadIdx.x < 64) sb1[threadIdx.x] = b1[threadIdx.x];
    if (threadIdx.x < 16) sb2[threadIdx.x] = b2[threadIdx.x];
    __syncthreads();

    int e = blockIdx.x * blockDim.x + threadIdx.x;
    if (e >= E) return;
    int s = ei[e];
    int d = ei[E + e];
    if ((unsigned)s >= (unsigned)n || (unsigned)d >= (unsigned)n) return;

    // in[0..15] = x[src], in[16..31] = x[dst]
    float in[32];
    {
        const float4* ps = (const float4*)(x + (size_t)s * NDIM);
        const float4* pd = (const float4*)(x + (size_t)d * NDIM);
        #pragma unroll
        for (int q = 0; q < 4; q++) {
            float4 v = ps[q];
            in[4 * q + 0] = v.x; in[4 * q + 1] = v.y;
            in[4 * q + 2] = v.z; in[4 * q + 3] = v.w;
        }
        #pragma unroll
        for (int q = 0; q < 4; q++) {
            float4 v = pd[q];
            in[16 + 4 * q + 0] = v.x; in[16 + 4 * q + 1] = v.y;
            in[16 + 4 * q + 2] = v.z; in[16 + 4 * q + 3] = v.w;
        }
    }

    // v0 = MLP([xs,xd]), v1 = MLP([xd,xs]); both dirs share every weight load.
    float v0[16], v1[16];
    #pragma unroll
    for (int i = 0; i < 16; i++) { v0[i] = sb2[i]; v1[i] = sb2[i]; }

    #pragma unroll 1
    for (int jj = 0; jj < 64; jj += 8) {
        float h0[8], h1[8];
        #pragma unroll
        for (int j = 0; j < 8; j++) {
            float b = sb1[jj + j];
            h0[j] = b; h1[j] = b;
        }
        #pragma unroll
        for (int k = 0; k < 32; k++) {
            const float4* wp = (const float4*)(sW1 + k * 64 + jj);  // broadcast LDS.128 x2
            float4 wa = wp[0], wb = wp[1];
            float a0 = in[k];        // dir0 input
            float a1 = in[k ^ 16];   // dir1 input (swapped halves)
            h0[0] += wa.x * a0; h1[0] += wa.x * a1;
            h0[1] += wa.y * a0; h1[1] += wa.y * a1;
            h0[2] += wa.z * a0; h1[2] += wa.z * a1;
            h0[3] += wa.w * a0; h1[3] += wa.w * a1;
            h0[4] += wb.x * a0; h1[4] += wb.x * a1;
            h0[5] += wb.y * a0; h1[5] += wb.y * a1;
            h0[6] += wb.z * a0; h1[6] += wb.z * a1;
            h0[7] += wb.w * a0; h1[7] += wb.w * a1;
        }
        #pragma unroll
        for (int j = 0; j < 8; j++) {
            h0[j] = fmaxf(h0[j], 0.f);
            h1[j] = fmaxf(h1[j], 0.f);
        }
        #pragma unroll
        for (int i = 0; i < 16; i++) {
            const float4* wp = (const float4*)(sW2 + i * 64 + jj);  // broadcast LDS.128 x2
            float4 wa = wp[0], wb = wp[1];
            v0[i] += wa.x * h0[0] + wa.y * h0[1] + wa.z * h0[2] + wa.w * h0[3]
                   + wb.x * h0[4] + wb.y * h0[5] + wb.z * h0[6] + wb.w * h0[7];
            v1[i] += wa.x * h1[0] + wa.y * h1[1] + wa.z * h1[2] + wa.w * h1[3]
                   + wb.x * h1[4] + wb.y * h1[5] + wb.z * h1[6] + wb.w * h1[7];
        }
    }

    // normalize: u = v / max(||v||, 1e-12)
    float n0 = 0.f, n1 = 0.f;
    #pragma unroll
    for (int i = 0; i < 16; i++) { n0 += v0[i] * v0[i]; n1 += v1[i] * v1[i]; }
    float inv0 = 1.f / fmaxf(sqrtf(n0), 1e-12f);
    float inv1 = 1.f / fmaxf(sqrtf(n1), 1e-12f);
    #pragma unroll
    for (int i = 0; i < 16; i++) { v0[i] *= inv0; v1[i] *= inv1; }
    // v0 = u_src (Householder vec of F_s), v1 = u_dst (F_d)

    float coef = g_dinv[s] * g_dinv[d];

    // message to src: += coef * F_s(F_d x_d);  F u y = y - 2(u.y)u
    {
        float t[16];
        float dd = 0.f;
        #pragma unroll
        for (int i = 0; i < 16; i++) dd += v1[i] * in[16 + i];
        dd *= 2.f;
        #pragma unroll
        for (int i = 0; i < 16; i++) t[i] = in[16 + i] - dd * v1[i];
        float ds = 0.f;
        #pragma unroll
        for (int i = 0; i < 16; i++) ds += v0[i] * t[i];
        ds *= 2.f;
        float* po = out + (size_t)s * NDIM;
        #pragma unroll
        for (int i = 0; i < 16; i++) atomicAdd(po + i, coef * (t[i] - ds * v0[i]));
    }

    // message to dst: += coef * F_d(F_s x_s)
    {
        float t[16];
        float ss = 0.f;
        #pragma unroll
        for (int i = 0; i < 16; i++) ss += v0[i] * in[i];
        ss *= 2.f;
        #pragma unroll
        for (int i = 0; i < 16; i++) t[i] = in[i] - ss * v0[i];
        float sd = 0.f;
        #pragma unroll
        for (int i = 0; i < 16; i++) sd += v1[i] * t[i];
        sd *= 2.f;
        float* pq = out + (size_t)d * NDIM;
        #pragma unroll
        for (int i = 0; i < 16; i++) atomicAdd(pq + i, coef * (t[i] - sd * v1[i]));
    }
}

extern "C" void kernel_launch(void* const* d_in, const int* in_sizes, int n_in,
                              void* d_out, int out_size) {
    const float* x  = (const float*)d_in[0];
    const int*   ei = (const int*)d_in[1];
    const float* W1 = (const float*)d_in[2];
    const float* b1 = (const float*)d_in[3];
    const float* W2 = (const float*)d_in[4];
    const float* b2 = (const float*)d_in[5];
    float* out = (float*)d_out;

    int n  = in_sizes[0] / NDIM;
    int E  = in_sizes[1] / 2;
    int nd = n * NDIM;

    init_kernel<<<(nd + 255) / 256, 256>>>(x, out, n);
    deg_kernel<<<(E + 255) / 256, 256>>>(ei, E, n);
    dinv_kernel<<<(n + 255) / 256, 256>>>(n);
    edge_kernel<<<(E + 127) / 128, 128>>>(x, ei, W1, b1, W2, b2, out, E, n);
    relu_kernel<<<(nd + 255) / 256, 256>>>(out, nd);
}